// round 12
// baseline (speedup 1.0000x reference)
#include <cuda_runtime.h>
#include <cuda_bf16.h>
#define EPSF 1e-20f

static constexpr long N512 = 2L * 32 * 512 * 512;
static constexpr long N256 = N512 / 4;
static constexpr long N128 = N512 / 16;
static constexpr long N64  = N512 / 64;
static constexpr long POOL_FLOATS =
    3 * N512 + 4 * N256 + 3 * N128 + 2 * N64 + 4096 + 2 * 12800 + 3 * 9216 + 512;

__device__ __align__(16) float g_pool[POOL_FLOATS];

// ---------------- helpers ----------------
__device__ __forceinline__ void cp_async16(unsigned dst, const void* src) {
    asm volatile("cp.async.cg.shared.global [%0], [%1], 16;\n" :: "r"(dst), "l"(src));
}
__device__ __forceinline__ void cp_async16z(unsigned dst, const void* src, bool v) {
    int sz = v ? 16 : 0;
    asm volatile("cp.async.cg.shared.global [%0], [%1], 16, %2;\n"
                 :: "r"(dst), "l"(src), "r"(sz));
}
__device__ __forceinline__ void cp_commit() { asm volatile("cp.async.commit_group;\n"); }
template <int N>
__device__ __forceinline__ void cp_wait() {
    asm volatile("cp.async.wait_group %0;\n" :: "n"(N));
}
__device__ __forceinline__ unsigned bfp(float lo, float hi) {
    __nv_bfloat162 v = __floats2bfloat162_rn(lo, hi);
    return *reinterpret_cast<unsigned*>(&v);
}
__device__ __forceinline__ void ldsm4(unsigned& r0, unsigned& r1, unsigned& r2,
                                      unsigned& r3, unsigned addr) {
    asm volatile("ldmatrix.sync.aligned.m8n8.x4.shared.b16 {%0,%1,%2,%3}, [%4];"
                 : "=r"(r0), "=r"(r1), "=r"(r2), "=r"(r3) : "r"(addr));
}
__device__ __forceinline__ void mma16(float* d, unsigned a0, unsigned a1, unsigned a2,
                                      unsigned a3, unsigned b0, unsigned b1) {
    asm("mma.sync.aligned.m16n8k16.row.col.f32.bf16.bf16.f32 "
        "{%0,%1,%2,%3},{%4,%5,%6,%7},{%8,%9},{%0,%1,%2,%3};"
        : "+f"(d[0]), "+f"(d[1]), "+f"(d[2]), "+f"(d[3])
        : "r"(a0), "r"(a1), "r"(a2), "r"(a3), "r"(b0), "r"(b1));
}

// bf16 MMA over all taps of one 16-ci chunk.
// A: [pix][32B] with 16B-half swizzle keyed on pixel bit 2 (unchanged).
// B: per tap, 8 contiguous 8x8 bf16 matrices [h*4+nf][row=co][16B], loaded
//    with 2 ldmatrix.x4 (lanes 0-7 -> mat0 rows, ... standard).
template <int KS, int SW>
__device__ __forceinline__ void mma_taps_bf16(unsigned w_s, unsigned pxc_s,
                                              unsigned pc_s, int wy, int lane,
                                              float (&accN)[2][4][4],
                                              float (&accD)[2][4][4]) {
    const int pxoff = ((lane >> 3) & 1) * 8 + (lane & 7);
    const int hbit = (lane >> 4) & 1;
    const unsigned bsub = (unsigned)(((lane >> 3) << 7) + ((lane & 7) << 4));
#pragma unroll
    for (int ky = 0; ky < KS; ky++) {
#pragma unroll
        for (int kx = 0; kx < KS; kx++) {
            const int kk = ky * KS + kx;
            unsigned b0[4], b1[4];
            ldsm4(b0[0], b0[1], b0[2], b0[3], w_s + kk * 1024 + bsub);
            ldsm4(b1[0], b1[1], b1[2], b1[3], w_s + kk * 1024 + 512 + bsub);
#pragma unroll
            for (int mf = 0; mf < 2; mf++) {
                const int p = (wy + ky) * SW + mf * 16 + kx + pxoff;
                const unsigned off = p * 32 + ((((p >> 2) ^ hbit) & 1) << 4);
                unsigned ax0, ax1, ax2, ax3, ac0, ac1, ac2, ac3;
                ldsm4(ax0, ax1, ax2, ax3, pxc_s + off);
                ldsm4(ac0, ac1, ac2, ac3, pc_s + off);
#pragma unroll
                for (int nf = 0; nf < 4; nf++) {
                    mma16(accN[mf][nf], ax0, ax1, ax2, ax3, b0[nf], b1[nf]);
                    mma16(accD[mf][nf], ac0, ac1, ac2, ac3, b0[nf], b1[nf]);
                }
            }
        }
    }
}

// epilogue -> packed bf16 [pix][64B xc | 64B c]
__device__ __forceinline__ void epi_packed(float (&aN)[2][4][4], float (&aD)[2][4][4],
                                           const float* bias, const float* winv,
                                           char* out, long PLANE, int WW,
                                           int bz, int y, int bx, int g, int t) {
    char* ob = out + ((long)bz * PLANE + (long)y * WW) * 128;
#pragma unroll
    for (int mf = 0; mf < 2; mf++) {
        const int px0 = bx + mf * 16 + g;
#pragma unroll
        for (int nf = 0; nf < 4; nf++) {
            const int co = nf * 8 + 2 * t;
            const float bi0 = bias[co], bi1 = bias[co + 1];
            const float wv0 = winv[co], wv1 = winv[co + 1];
            float* n = aN[mf][nf];
            float* d = aD[mf][nf];
            float x00 = n[0] / (d[0] + EPSF) + bi0, c00 = d[0] * wv0;
            float x01 = n[1] / (d[1] + EPSF) + bi1, c01 = d[1] * wv1;
            float x10 = n[2] / (d[2] + EPSF) + bi0, c10 = d[2] * wv0;
            float x11 = n[3] / (d[3] + EPSF) + bi1, c11 = d[3] * wv1;
            const int wo = nf * 16 + t * 4;
            *(unsigned*)(ob + (long)px0 * 128 + wo)            = bfp(x00 * c00, x01 * c01);
            *(unsigned*)(ob + (long)px0 * 128 + 64 + wo)       = bfp(c00, c01);
            *(unsigned*)(ob + (long)(px0 + 8) * 128 + wo)      = bfp(x10 * c10, x11 * c11);
            *(unsigned*)(ob + (long)(px0 + 8) * 128 + 64 + wo) = bfp(c10, c11);
        }
    }
}

// ---------------- small kernels ----------------
__global__ void wsum_kernel(const float* __restrict__ w1, const float* __restrict__ w2,
                            const float* __restrict__ w3, const float* __restrict__ w4,
                            const float* __restrict__ w5, const float* __restrict__ w6,
                            const float* __restrict__ w7, float* __restrict__ inv) {
    int l = blockIdx.x, co = threadIdx.x;
    const float* w; int n; int nco = 32;
    if      (l == 0) { w = w1; n = 1 * 25; }
    else if (l == 1) { w = w2; n = 32 * 25; }
    else if (l == 2) { w = w3; n = 32 * 25; }
    else if (l == 3) { w = w4; n = 64 * 9; }
    else if (l == 4) { w = w5; n = 64 * 9; }
    else if (l == 5) { w = w6; n = 64 * 9; }
    else             { w = w7; n = 32;  nco = 1; }
    if (co >= nco) return;
    float s = 0.f;
    for (int i = 0; i < n; i++) s += w[co * n + i];
    inv[l * 32 + co] = 1.0f / s;
}

// weight prep for ldmatrix B: OIHW -> bf16 [chunk][kk][h*4+nf][row g(co)][8 ci]
__global__ void prep_w_ldsm(const float* __restrict__ w, __nv_bfloat16* __restrict__ dst,
                            int CIN, int KK, int total) {
    int i = blockIdx.x * 256 + threadIdx.x;
    if (i >= total) return;
    int e = i & 7;             // ci low (t*2+lo)
    int g = (i >> 3) & 7;      // co low
    int m = (i >> 6) & 7;      // h*4+nf
    int r = i >> 9;            // chunk*KK + kk
    int kk = r % KK, ch = r / KK;
    int h = m >> 2, nf = m & 3;
    int co = nf * 8 + g;
    int ci = ch * 16 + h * 8 + e;
    dst[i] = __float2bfloat16(w[((long)co * CIN + ci) * KK + kk]);
}

// w1 prep: taps (25, pad to 32) as the "ci" axis, KK=1, 2 chunks
__global__ void prep_w1_ldsm(const float* __restrict__ w, __nv_bfloat16* __restrict__ dst) {
    int i = blockIdx.x * 256 + threadIdx.x;
    if (i >= 1024) return;
    int e = i & 7, g = (i >> 3) & 7, m = (i >> 6) & 7, ch = i >> 9;
    int h = m >> 2, nf = m & 3;
    int co = nf * 8 + g;
    int tap = ch * 16 + h * 8 + e;
    dst[i] = __float2bfloat16(tap < 25 ? w[co * 25 + tap] : 0.f);
}

// pool on packed tensors: per-channel 2x2 argmax of c, gather xc, /4
__global__ void pool_p(const char* __restrict__ in, char* __restrict__ out,
                       int Ho, int Wo) {
    int idx = blockIdx.x * 256 + threadIdx.x;
    int total = 2 * Ho * Wo * 2;
    if (idx >= total) return;
    int chunk = idx & 1;
    int r = idx >> 1;
    int xo = r % Wo; r /= Wo;
    int yo = r % Ho; int b = r / Ho;
    int Wi = Wo * 2;
    const char* ib = in + ((long)b * 4 * Ho * Wo + (long)(2 * yo) * Wi + 2 * xo) * 128;
    long poff[4] = {0, 128, (long)Wi * 128, (long)Wi * 128 + 128};
    unsigned cw[4][8], xw[4][8];
#pragma unroll
    for (int k = 0; k < 4; k++) {
        uint4 a = *(const uint4*)(ib + poff[k] + 64 + chunk * 32);
        uint4 bq = *(const uint4*)(ib + poff[k] + 80 + chunk * 32);
        cw[k][0] = a.x; cw[k][1] = a.y; cw[k][2] = a.z; cw[k][3] = a.w;
        cw[k][4] = bq.x; cw[k][5] = bq.y; cw[k][6] = bq.z; cw[k][7] = bq.w;
        a = *(const uint4*)(ib + poff[k] + chunk * 32);
        bq = *(const uint4*)(ib + poff[k] + 16 + chunk * 32);
        xw[k][0] = a.x; xw[k][1] = a.y; xw[k][2] = a.z; xw[k][3] = a.w;
        xw[k][4] = bq.x; xw[k][5] = bq.y; xw[k][6] = bq.z; xw[k][7] = bq.w;
    }
    unsigned oc[8], ox[8];
#pragma unroll
    for (int w = 0; w < 8; w++) {
        float bl = -1e30f, bh = -1e30f; int kl = 0, kh = 0;
#pragma unroll
        for (int k = 0; k < 4; k++) {
            __nv_bfloat162 v = *reinterpret_cast<__nv_bfloat162*>(&cw[k][w]);
            float2 f = __bfloat1622float2(v);
            if (f.x > bl) { bl = f.x; kl = k; }
            if (f.y > bh) { bh = f.y; kh = k; }
        }
        oc[w] = bfp(bl * 0.25f, bh * 0.25f);
        __nv_bfloat162 xl = *reinterpret_cast<__nv_bfloat162*>(&xw[kl][w]);
        __nv_bfloat162 xh = *reinterpret_cast<__nv_bfloat162*>(&xw[kh][w]);
        ox[w] = bfp(__low2float(xl) * 0.25f, __high2float(xh) * 0.25f);
    }
    char* ob = out + ((long)b * Ho * Wo + (long)yo * Wo + xo) * 128;
    *(uint4*)(ob + chunk * 32)      = make_uint4(ox[0], ox[1], ox[2], ox[3]);
    *(uint4*)(ob + 16 + chunk * 32) = make_uint4(ox[4], ox[5], ox[6], ox[7]);
    *(uint4*)(ob + 64 + chunk * 32) = make_uint4(oc[0], oc[1], oc[2], oc[3]);
    *(uint4*)(ob + 80 + chunk * 32) = make_uint4(oc[4], oc[5], oc[6], oc[7]);
}

// layer1 via im2col MMA: 5x5, CIN=1 -> 32. A = [pixel][32 taps(bf16)], B = w1 taps x co.
template <int HH, int WW>
__global__ __launch_bounds__(256)
void nconv_l1_mma(const float* __restrict__ xin, const float* __restrict__ cin,
                  long bstride, const unsigned short* __restrict__ w1p,
                  const float* __restrict__ bias, const float* __restrict__ winv,
                  char* __restrict__ out) {
    constexpr int PAD = 2, SWH = 36, NS = SWH * 12;
    constexpr long PLANE = (long)HH * WW;
    __shared__ float cs[NS], xcs[NS];
    __shared__ __align__(16) char pA[256 * 32];
    __shared__ __align__(16) char pC[256 * 32];
    __shared__ __align__(16) char wsb[2048];
    const int tid = threadIdx.x, wy = tid >> 5, lane = tid & 31;
    const int g = lane >> 2, t = lane & 3;
    const int tx = tid & 31, ty = tid >> 5;
    const int bx = blockIdx.x * 32, by = blockIdx.y * 8, b = blockIdx.z;

    if (tid < 128) ((uint4*)wsb)[tid] = ((const uint4*)w1p)[tid];
    const float* xp = xin + (long)b * bstride;
    const float* cp = cin + (long)b * bstride;
    for (int i = tid; i < NS; i += 256) {
        int r = i / SWH, c = i - r * SWH;
        int gy = by + r - PAD, gx = bx + c - PAD;
        float cv = 0.f, xv = 0.f;
        if ((unsigned)gy < (unsigned)HH && (unsigned)gx < (unsigned)WW) {
            long gg = (long)gy * WW + gx;
            cv = cp[gg]; xv = xp[gg];
        }
        cs[i] = cv; xcs[i] = xv * cv;
    }

    float accN[2][4][4] = {}, accD[2][4][4] = {};
    const unsigned pA_s = (unsigned)__cvta_generic_to_shared(pA);
    const unsigned pC_s = (unsigned)__cvta_generic_to_shared(pC);
    const unsigned w_s = (unsigned)__cvta_generic_to_shared(wsb);
    const int base = ty * SWH + tx;
    const int hsw = (tid >> 2) & 1;

#pragma unroll
    for (int ch = 0; ch < 2; ch++) {
        __syncthreads();
#pragma unroll
        for (int h = 0; h < 2; h++) {
            unsigned wx[4], wc[4];
#pragma unroll
            for (int w2 = 0; w2 < 4; w2++) {
                const int t0 = ch * 16 + h * 8 + 2 * w2;
                float x0 = 0.f, c0 = 0.f, x1 = 0.f, c1 = 0.f;
                if (t0 < 25) { int o = base + (t0 / 5) * SWH + (t0 % 5); x0 = xcs[o]; c0 = cs[o]; }
                if (t0 + 1 < 25) { int o = base + ((t0 + 1) / 5) * SWH + ((t0 + 1) % 5); x1 = xcs[o]; c1 = cs[o]; }
                wx[w2] = bfp(x0, x1); wc[w2] = bfp(c0, c1);
            }
            const int off = tid * 32 + ((h ^ hsw) << 4);
            *(uint4*)(pA + off) = make_uint4(wx[0], wx[1], wx[2], wx[3]);
            *(uint4*)(pC + off) = make_uint4(wc[0], wc[1], wc[2], wc[3]);
        }
        __syncthreads();
        mma_taps_bf16<1, 32>(w_s + ch * 1024, pA_s, pC_s, wy, lane, accN, accD);
    }
    epi_packed(accN, accD, bias, winv, out, PLANE, WW, b, by + wy, bx, g, t);
}

// ---------- packed bf16 tensor-core encoder nconv: 5x5, 32->32 ----------
template <int HH, int WW>
__global__ __launch_bounds__(256, 2)
void nconv_mma_p(const char* __restrict__ in, const unsigned short* __restrict__ wp,
                 const float* __restrict__ bias, const float* __restrict__ winv,
                 char* __restrict__ out) {
    constexpr int KS = 5, PAD = 2, SW = 36, SH = 12, NS = SH * SW, NS32 = NS * 32;
    constexpr int NCH = 2, WALLB = NCH * 25 * 1024;
    constexpr long PLANE = (long)HH * WW;
    extern __shared__ char dsmc[];
    char* inbuf = dsmc;                 // 2 bufs x (pxc NS32 + pc NS32)
    char* wsb = dsmc + 2 * 2 * NS32;    // WALLB

    const int tid = threadIdx.x, wy = tid >> 5, lane = tid & 31;
    const int g = lane >> 2, t = lane & 3;
    const int bx = blockIdx.x * 32, by = blockIdx.y * 8, bz = blockIdx.z;

    const char* inb = in + (long)bz * PLANE * 128;
    const unsigned in_s = (unsigned)__cvta_generic_to_shared(inbuf);
    const unsigned ws_s = (unsigned)__cvta_generic_to_shared(wsb);

    auto stage_in = [&](int ch, int buf) {
        const unsigned dstb = in_s + buf * (2 * NS32);
        for (int i = tid; i < NS * 4; i += 256) {
            const int p = i >> 2, q = i & 3, h = q & 1, tz = q >> 1;
            const int r = p / SW, c = p - r * SW;
            const int gy = by + r - PAD, gx = bx + c - PAD;
            const bool v = (unsigned)gy < (unsigned)HH && (unsigned)gx < (unsigned)WW;
            const long gp = v ? (long)gy * WW + gx : 0;
            unsigned dst = dstb + tz * NS32 + p * 32 + ((h ^ ((p >> 2) & 1)) << 4);
            cp_async16z(dst, inb + gp * 128 + tz * 64 + ch * 32 + h * 16, v);
        }
    };

    for (int i = tid; i < WALLB / 16; i += 256)
        cp_async16(ws_s + i * 16, (const char*)wp + i * 16);
    stage_in(0, 0);
    cp_commit();

    float accN[2][4][4] = {}, accD[2][4][4] = {};
#pragma unroll 1
    for (int ch = 0; ch < NCH; ch++) {
        cp_wait<0>();
        __syncthreads();
        if (ch + 1 < NCH) { stage_in(ch + 1, (ch + 1) & 1); cp_commit(); }
        const unsigned pxc_s = in_s + (ch & 1) * (2 * NS32);
        mma_taps_bf16<KS, SW>(ws_s + ch * 25 * 1024, pxc_s, pxc_s + NS32, wy, lane,
                              accN, accD);
    }
    epi_packed(accN, accD, bias, winv, out, PLANE, WW, bz, by + wy, bx, g, t);
}

// ---- packed bf16 decoder nconv: 3x3, 64->32, cat + up2; optional fused 1x1 ----
template <int HH, int WW, bool FUSE>
__global__ __launch_bounds__(256, 2)
void nconv_cat_mma_p(const char* __restrict__ in0, int half0,
                     const char* __restrict__ in1, int half1,
                     const unsigned short* __restrict__ wp,
                     const float* __restrict__ bias, const float* __restrict__ winv,
                     char* __restrict__ out,
                     const float* __restrict__ w7, const float* __restrict__ b7,
                     float* __restrict__ fout) {
    constexpr int KS = 3, PAD = 1, SW = 34, SH = 10, NS = SH * SW, NS32 = NS * 32;
    constexpr int NCH = 4, WALLB = NCH * 9 * 1024;
    constexpr int W2 = WW / 2;
    constexpr long PLANE = (long)HH * WW;
    extern __shared__ char dsmc[];
    char* inbuf = dsmc;
    char* wsb = dsmc + 2 * 2 * NS32;

    const int tid = threadIdx.x, wy = tid >> 5, lane = tid & 31;
    const int g = lane >> 2, t = lane & 3;
    const int bx = blockIdx.x * 32, by = blockIdx.y * 8, bz = blockIdx.z;

    const unsigned in_s = (unsigned)__cvta_generic_to_shared(inbuf);
    const unsigned ws_s = (unsigned)__cvta_generic_to_shared(wsb);

    auto stage_in = [&](int ch, int buf) {
        const int grp = ch >> 1;
        const char* src = (grp ? in1 : in0);
        const int half = grp ? half1 : half0;
        const long plane = half ? (long)(HH / 2) * W2 : PLANE;
        const char* sb = src + (long)bz * plane * 128;
        const int chl = ch & 1;
        const unsigned dstb = in_s + buf * (2 * NS32);
        for (int i = tid; i < NS * 4; i += 256) {
            const int p = i >> 2, q = i & 3, h = q & 1, tz = q >> 1;
            const int r = p / SW, c = p - r * SW;
            const int gy = by + r - PAD, gx = bx + c - PAD;
            const bool v = (unsigned)gy < (unsigned)HH && (unsigned)gx < (unsigned)WW;
            const long gp = v ? (half ? (long)(gy >> 1) * W2 + (gx >> 1)
                                      : (long)gy * WW + gx) : 0;
            unsigned dst = dstb + tz * NS32 + p * 32 + ((h ^ ((p >> 2) & 1)) << 4);
            cp_async16z(dst, sb + gp * 128 + tz * 64 + chl * 32 + h * 16, v);
        }
    };

    for (int i = tid; i < WALLB / 16; i += 256)
        cp_async16(ws_s + i * 16, (const char*)wp + i * 16);
    stage_in(0, 0);
    cp_commit();

    float accN[2][4][4] = {}, accD[2][4][4] = {};
#pragma unroll 1
    for (int ch = 0; ch < NCH; ch++) {
        cp_wait<0>();
        __syncthreads();
        if (ch + 1 < NCH) { stage_in(ch + 1, (ch + 1) & 1); cp_commit(); }
        const unsigned pxc_s = in_s + (ch & 1) * (2 * NS32);
        mma_taps_bf16<KS, SW>(ws_s + ch * 9 * 1024, pxc_s, pxc_s + NS32, wy, lane,
                              accN, accD);
    }

    const int y = by + wy;
    if (!FUSE) {
        epi_packed(accN, accD, bias, winv, out, PLANE, WW, bz, y, bx, g, t);
    } else {
        float w7a[4], w7b[4];
#pragma unroll
        for (int nf = 0; nf < 4; nf++) {
            w7a[nf] = __ldg(w7 + nf * 8 + 2 * t);
            w7b[nf] = __ldg(w7 + nf * 8 + 2 * t + 1);
        }
        const float b7v = __ldg(b7);
#pragma unroll
        for (int mf = 0; mf < 2; mf++) {
            float ns0 = 0.f, ds0 = 0.f, ns1 = 0.f, ds1 = 0.f;
#pragma unroll
            for (int nf = 0; nf < 4; nf++) {
                const int co = nf * 8 + 2 * t;
                float* n = accN[mf][nf];
                float* d = accD[mf][nf];
                float x00 = n[0] / (d[0] + EPSF) + bias[co],     c00 = d[0] * winv[co];
                float x01 = n[1] / (d[1] + EPSF) + bias[co + 1], c01 = d[1] * winv[co + 1];
                float x10 = n[2] / (d[2] + EPSF) + bias[co],     c10 = d[2] * winv[co];
                float x11 = n[3] / (d[3] + EPSF) + bias[co + 1], c11 = d[3] * winv[co + 1];
                ns0 += w7a[nf] * x00 * c00 + w7b[nf] * x01 * c01;
                ds0 += w7a[nf] * c00 + w7b[nf] * c01;
                ns1 += w7a[nf] * x10 * c10 + w7b[nf] * x11 * c11;
                ds1 += w7a[nf] * c10 + w7b[nf] * c11;
            }
#pragma unroll
            for (int s = 1; s <= 2; s <<= 1) {
                ns0 += __shfl_xor_sync(0xffffffffu, ns0, s);
                ds0 += __shfl_xor_sync(0xffffffffu, ds0, s);
                ns1 += __shfl_xor_sync(0xffffffffu, ns1, s);
                ds1 += __shfl_xor_sync(0xffffffffu, ds1, s);
            }
            if (t == 0) {
                const long base = (long)bz * PLANE + (long)y * WW + bx + mf * 16 + g;
                fout[base]     = ns0 / (ds0 + EPSF) + b7v;
                fout[base + 8] = ns1 / (ds1 + EPSF) + b7v;
            }
        }
    }
}

// ---------------- launch ----------------
static constexpr int SMEM_ENC = 4 * 432 * 32 + 2 * 25 * 1024;  // 106496
static constexpr int SMEM_DEC = 4 * 340 * 32 + 4 * 9 * 1024;   // 80384

extern "C" void kernel_launch(void* const* d_in, const int* in_sizes, int n_in,
                              void* d_out, int out_size) {
    const float* x  = (const float*)d_in[0];
    const float* w1 = (const float*)d_in[1];  const float* b1 = (const float*)d_in[2];
    const float* w2 = (const float*)d_in[3];  const float* b2 = (const float*)d_in[4];
    const float* w3 = (const float*)d_in[5];  const float* b3 = (const float*)d_in[6];
    const float* w4 = (const float*)d_in[7];  const float* b4 = (const float*)d_in[8];
    const float* w5 = (const float*)d_in[9];  const float* b5 = (const float*)d_in[10];
    const float* w6 = (const float*)d_in[11]; const float* b6 = (const float*)d_in[12];
    const float* w7 = (const float*)d_in[13]; const float* b7 = (const float*)d_in[14];

    float* pool = nullptr;
    cudaGetSymbolAddress((void**)&pool, g_pool);

    char* F512a = (char*)(pool);
    char* F512b = (char*)(pool + N512);
    char* F512s = (char*)(pool + 2 * N512);
    char* F256a = (char*)(pool + 3 * N512);
    char* F256b = (char*)(pool + 3 * N512 + N256);
    char* F256s = (char*)(pool + 3 * N512 + 2 * N256);
    char* D256  = (char*)(pool + 3 * N512 + 3 * N256);
    char* F128a = (char*)(pool + 3 * N512 + 4 * N256);
    char* F128s = (char*)(pool + 3 * N512 + 4 * N256 + N128);
    char* D128  = (char*)(pool + 3 * N512 + 4 * N256 + 2 * N128);
    char* F64a  = (char*)(pool + 3 * N512 + 4 * N256 + 3 * N128);
    char* F64b  = (char*)(pool + 3 * N512 + 4 * N256 + 3 * N128 + N64);
    float* WS   = pool + 3 * N512 + 4 * N256 + 3 * N128 + 2 * N64;
    __nv_bfloat16* PW2 = (__nv_bfloat16*)(WS + 4096);
    __nv_bfloat16* PW3 = (__nv_bfloat16*)(WS + 4096 + 12800);
    __nv_bfloat16* PW4 = (__nv_bfloat16*)(WS + 4096 + 2 * 12800);
    __nv_bfloat16* PW5 = (__nv_bfloat16*)(WS + 4096 + 2 * 12800 + 9216);
    __nv_bfloat16* PW6 = (__nv_bfloat16*)(WS + 4096 + 2 * 12800 + 2 * 9216);
    __nv_bfloat16* PW1 = (__nv_bfloat16*)(WS + 4096 + 2 * 12800 + 3 * 9216);

    cudaFuncSetAttribute(nconv_mma_p<512, 512>, cudaFuncAttributeMaxDynamicSharedMemorySize, SMEM_ENC);
    cudaFuncSetAttribute(nconv_mma_p<256, 256>, cudaFuncAttributeMaxDynamicSharedMemorySize, SMEM_ENC);
    cudaFuncSetAttribute(nconv_mma_p<128, 128>, cudaFuncAttributeMaxDynamicSharedMemorySize, SMEM_ENC);
    cudaFuncSetAttribute(nconv_mma_p<64, 64>,   cudaFuncAttributeMaxDynamicSharedMemorySize, SMEM_ENC);
    cudaFuncSetAttribute(nconv_cat_mma_p<128, 128, false>, cudaFuncAttributeMaxDynamicSharedMemorySize, SMEM_DEC);
    cudaFuncSetAttribute(nconv_cat_mma_p<256, 256, false>, cudaFuncAttributeMaxDynamicSharedMemorySize, SMEM_DEC);
    cudaFuncSetAttribute(nconv_cat_mma_p<512, 512, true>,  cudaFuncAttributeMaxDynamicSharedMemorySize, SMEM_DEC);

    const long HW = 512L * 512;

    wsum_kernel<<<7, 32>>>(w1, w2, w3, w4, w5, w6, w7, WS);
    prep_w_ldsm<<<100, 256>>>(w2, PW2, 32, 25, 25600);
    prep_w_ldsm<<<100, 256>>>(w3, PW3, 32, 25, 25600);
    prep_w_ldsm<<<72, 256>>>(w4, PW4, 64, 9, 18432);
    prep_w_ldsm<<<72, 256>>>(w5, PW5, 64, 9, 18432);
    prep_w_ldsm<<<72, 256>>>(w6, PW6, 64, 9, 18432);
    prep_w1_ldsm<<<4, 256>>>(w1, PW1);

    // Encoder @512
    nconv_l1_mma<512, 512><<<dim3(16, 64, 2), 256>>>(
        x, x + HW, 2 * HW, (const unsigned short*)PW1, b1, WS, F512a);
    nconv_mma_p<512, 512><<<dim3(16, 64, 2), 256, SMEM_ENC>>>(
        F512a, (const unsigned short*)PW2, b2, WS + 32, F512b);
    nconv_mma_p<512, 512><<<dim3(16, 64, 2), 256, SMEM_ENC>>>(
        F512b, (const unsigned short*)PW3, b3, WS + 64, F512s);

    // Down 1 @256
    pool_p<<<(int)((2L * 256 * 256 * 2 + 255) / 256), 256>>>(F512s, F256a, 256, 256);
    nconv_mma_p<256, 256><<<dim3(8, 32, 2), 256, SMEM_ENC>>>(
        F256a, (const unsigned short*)PW2, b2, WS + 32, F256b);
    nconv_mma_p<256, 256><<<dim3(8, 32, 2), 256, SMEM_ENC>>>(
        F256b, (const unsigned short*)PW3, b3, WS + 64, F256s);

    // Down 2 @128
    pool_p<<<(int)((2L * 128 * 128 * 2 + 255) / 256), 256>>>(F256s, F128a, 128, 128);
    nconv_mma_p<128, 128><<<dim3(4, 16, 2), 256, SMEM_ENC>>>(
        F128a, (const unsigned short*)PW2, b2, WS + 32, F128s);

    // Down 3 @64
    pool_p<<<(int)((2L * 64 * 64 * 2 + 255) / 256), 256>>>(F128s, F64a, 64, 64);
    nconv_mma_p<64, 64><<<dim3(2, 8, 2), 256, SMEM_ENC>>>(
        F64a, (const unsigned short*)PW2, b2, WS + 32, F64b);

    // Decoder
    nconv_cat_mma_p<128, 128, false><<<dim3(4, 16, 2), 256, SMEM_DEC>>>(
        F128s, 0, F64b, 1, (const unsigned short*)PW4, b4, WS + 96, D128,
        nullptr, nullptr, nullptr);
    nconv_cat_mma_p<256, 256, false><<<dim3(8, 32, 2), 256, SMEM_DEC>>>(
        F256s, 0, D128, 1, (const unsigned short*)PW5, b5, WS + 128, D256,
        nullptr, nullptr, nullptr);
    nconv_cat_mma_p<512, 512, true><<<dim3(16, 64, 2), 256, SMEM_DEC>>>(
        D256, 1, F512s, 0, (const unsigned short*)PW6, b6, WS + 160, nullptr,
        w7, b7, (float*)d_out);
}